// round 17
// baseline (speedup 1.0000x reference)
#include <cuda_runtime.h>
#include <cuda_bf16.h>
#include <math.h>
#include <stdint.h>

// HierarchicalDistanceLoss — R17: R16 (best measured: 32.58us main, 5.47 TB/s)
// with incremental hot-loop addressing: running pointers for logits tiles,
// labels, and df stores (constant stride per iteration) replace per-iteration
// 64-bit IMAD.WIDE chains. ALU was the busiest pipe (34.9%).
// Warp-private 2-stage cp.async pipeline, 16-row warp-tiles, 2 lanes/row,
// balanced persistent grid, label register prefetch, fused last-block mean.
//   ce[b]  = log(sum exp(logits[b,:])) - logits[b, labels[b]]
//   pred   = argmax (first occurrence); df = dis[lab,pred]+0.5
//   out[0] = mean(ce*df), out[1..B] = df

#define CCOLS 40
#define TPB   128
#define WPB   4                        // warps per block
#define RPW   16                       // rows per warp-tile (2 lanes/row)
#define F4PT  (RPW * 10)               // 160 float4 = 2560 B per stage
#define GRIDB 1366                     // ~9.2 CTAs/SM, near-even tile split
#define NW    (GRIDB * WPB)            // 5464 warps
#define NWF4  (NW * F4PT)              // float4 stride between a warp's tiles
#define NWR   (NW * RPW)               // row stride between a warp's tiles

#define CP_CG16(dst, src) asm volatile("cp.async.cg.shared.global [%0], [%1], 16;" :: "r"(dst), "l"(src) : "memory")
#define CP_COMMIT()       asm volatile("cp.async.commit_group;" ::: "memory")
#define CP_WAIT1()        asm volatile("cp.async.wait_group 1;" ::: "memory")

__device__ float    g_partials[8192];
__device__ unsigned g_count;           // zero-init; last block resets

__global__ void __launch_bounds__(TPB, 10) hier_loss_r17(
    const float* __restrict__ logits,  // [B*40]
    const int*   __restrict__ labels,  // [B]
    const float* __restrict__ dis,     // [40*40]
    float*       __restrict__ out,     // [0] = loss
    float*       __restrict__ df_out,  // [B]
    float invB, int ntiles)            // ntiles = B/16
{
    __shared__ __align__(128) float4 tile[WPB][2][F4PT];   // 20480 B
    __shared__ float wsum[WPB];
    __shared__ int   isLast;

    const int tid  = threadIdx.x;
    const int wid  = tid >> 5;
    const int lane = tid & 31;
    const int half = lane & 1;         // 0: cols 0-19, 1: cols 20-39
    const int rrow = lane >> 1;        // row within tile (0..15)
    const int bid  = blockIdx.x;
    const int gw   = bid * WPB + wid;  // global warp id

    const int nmine = (ntiles - gw + NW - 1) / NW;   // 11 or 12 (balanced)

    const uint32_t t0 = (uint32_t)__cvta_generic_to_shared(&tile[wid][0][0]);

    // running pointers (64-bit init once; 64-bit ADD per advance thereafter)
    const float4* src4 = (const float4*)logits + (long long)gw * F4PT; // next issue
    const int*    labP = labels + (long long)gw * RPW + rrow;          // next prefetch
    float*        dfP  = df_out + (long long)gw * RPW + rrow;          // next store

    auto issue = [&](int s) {          // warp-cooperative, coalesced; consumes src4
        const uint32_t dst = t0 + (uint32_t)s * (F4PT * 16);
        #pragma unroll
        for (int i = 0; i < 5; ++i) {
            int idx = i * 32 + lane;
            CP_CG16(dst + (uint32_t)idx * 16u, src4 + idx);
        }
        src4 += NWF4;
    };

    int lab_q0 = 0, lab_q1 = 0;        // 2-deep label prefetch (even lanes)
    if (nmine > 0) {
        issue(0); CP_COMMIT();
        if (half == 0) lab_q0 = __ldcs(labP);
        labP += NWR;
    }
    if (nmine > 1) {
        issue(1); CP_COMMIT();
        if (half == 0) lab_q1 = __ldcs(labP);
        labP += NWR;
    }

    float acc = 0.0f;

    for (int j = 0; j < nmine; ++j) {
        const int s = j & 1;

        CP_WAIT1();                    // own oldest group complete
        __syncwarp();                  // cross-lane copy visibility (required)

        // lane covers floats [20*half, 20*half+20) of row rrow
        const float4* r   = &tile[wid][s][rrow * 10 + half * 5];
        const float*  row = (const float*)&tile[wid][s][rrow * 10];
        const int base = 20 * half;

        float m = -INFINITY, sum = 0.0f;
        int   am = base;
        #pragma unroll
        for (int i = 0; i < 5; ++i) {
            float4 v = r[i];
            if (v.x > m) { m = v.x; am = base + 4*i;   }
            if (v.y > m) { m = v.y; am = base + 4*i+1; }
            if (v.z > m) { m = v.z; am = base + 4*i+2; }
            if (v.w > m) { m = v.w; am = base + 4*i+3; }
            sum += (__expf(v.x) + __expf(v.y)) + (__expf(v.z) + __expf(v.w));
        }
        {   // pair merge (xor 1); tie -> smaller index = first occurrence
            float om = __shfl_xor_sync(0xffffffffu, m,  1);
            int   oa = __shfl_xor_sync(0xffffffffu, am, 1);
            if (om > m || (om == m && oa < am)) { m = om; am = oa; }
            sum += __shfl_xor_sync(0xffffffffu, sum, 1);
        }
        const float lse = __logf(sum);

        if (half == 0) {               // even lane finalizes its row
            const int lab = lab_q0;
            const float ce  = lse - row[lab];
            const float dfv = __ldg(&dis[lab * CCOLS + am]) + 0.5f;
            __stcs(dfP, dfv);
            acc += ce * dfv;
        }
        dfP += NWR;

        // rotate label queue; prefetch j+2 (hidden behind next tile's copy)
        lab_q0 = lab_q1;
        if (half == 0 && j + 2 < nmine) lab_q1 = __ldcs(labP);
        labP += NWR;

        // warp converged: stage-s reads architecturally complete; refill safely
        if (j + 2 < nmine) issue(s);
        CP_COMMIT();                   // uniform commits keep wait_group aligned
    }

    // ---- block reduction (deterministic) ----
    #pragma unroll
    for (int o = 16; o > 0; o >>= 1)
        acc += __shfl_down_sync(0xffffffffu, acc, o);
    if (lane == 0) wsum[wid] = acc;
    __syncthreads();
    if (tid == 0) {
        g_partials[bid] = (wsum[0] + wsum[1]) + (wsum[2] + wsum[3]);
        __threadfence();
        isLast = (atomicAdd(&g_count, 1u) == (unsigned)(GRIDB - 1));
    }
    __syncthreads();

    // ---- last-block-done final mean: independent unrolled loads ----
    if (isLast) {
        float part[11];                          // ceil(1366/128) = 11
        #pragma unroll
        for (int k = 0; k < 11; ++k) {
            int i = tid + k * TPB;
            part[k] = (i < GRIDB) ? g_partials[i] : 0.0f;
        }
        float t = 0.0f;
        #pragma unroll
        for (int k = 0; k < 11; ++k) t += part[k];

        #pragma unroll
        for (int o = 16; o > 0; o >>= 1)
            t += __shfl_down_sync(0xffffffffu, t, o);
        __shared__ float fsum[WPB];
        if (lane == 0) fsum[wid] = t;
        __syncthreads();
        if (tid == 0) {
            out[0] = ((fsum[0] + fsum[1]) + (fsum[2] + fsum[3])) * invB;
            g_count = 0;               // reset for graph replay
        }
    }
}

extern "C" void kernel_launch(void* const* d_in, const int* in_sizes, int n_in,
                              void* d_out, int out_size)
{
    const float* logits = (const float*)d_in[0];
    const int*   labels = (const int*)d_in[1];
    const float* dis    = (const float*)d_in[2];
    float* out = (float*)d_out;

    const long long B = (long long)in_sizes[1];     // 1048576
    const int ntiles = (int)(B / RPW);              // 65536

    const int off = out_size - (int)B;              // [loss, df...] layout
    float* dfo = out + (off > 0 ? off : 0);

    hier_loss_r17<<<GRIDB, TPB>>>(logits, labels, dis, out, dfo,
                                  1.0f / (float)B, ntiles);
}